// round 8
// baseline (speedup 1.0000x reference)
#include <cuda_runtime.h>
#include <math.h>

#define BB   2
#define LL   2048
#define DD   1024
#define NHH  16
#define KVHH 8
#define DHH  64

// ---------------- scratch (device globals; no allocation allowed) ----------
__device__ float g_q[(size_t)BB * NHH * LL * DHH];      // 16 MB  [b][h][l][dh]
__device__ float g_k[(size_t)BB * KVHH * LL * DHH];     // 8 MB   [b][kh][l][dh]
__device__ float g_v[(size_t)BB * KVHH * LL * DHH];     // 8 MB   [b][kh][l][dh]
__device__ float g_attn[(size_t)BB * LL * NHH * DHH];   // 16 MB  [b][l][h*64+dh]
__device__ float g_scores[(size_t)BB * NHH * LL * LL];  // 536 MB [bh][q][k]

// ---------------------------------------------------------------------------
// Generic tiled fp32 GEMM: C[M,N] = A[M,K] @ B[K,N] (row-major).
// Chunked accumulation (flush every 128 k) to reduce rounding random-walk.
// dst < 0 : write Cext row-major.
// dst >= 0: head-split epilogue into g_q/g_k/g_v with H heads.
// a_sel=1 : A comes from g_attn instead of Aext.
// ---------------------------------------------------------------------------
__global__ __launch_bounds__(256) void gemm_plain(
    const float* __restrict__ Aext, const float* __restrict__ Bm,
    float* __restrict__ Cext, int M, int N, int K,
    int a_sel, int dst, int H)
{
    __shared__ float As[16][64];
    __shared__ float Bs[16][64];
    const float* A = a_sel ? g_attn : Aext;

    int t  = threadIdx.x;
    int tx = t & 15, ty = t >> 4;
    int rowBase = blockIdx.y * 64;
    int colBase = blockIdx.x * 64;

    int aRow = t >> 2;          // 0..63
    int aK4  = (t & 3) * 4;     // 0,4,8,12
    int bK   = t >> 4;          // 0..15
    int bC4  = (t & 15) * 4;    // 0..60

    float acc[4][4] = {};
    float loc[4][4] = {};
    int tile = 0;

    for (int k0 = 0; k0 < K; k0 += 16) {
        float4 av = *(const float4*)&A[(size_t)(rowBase + aRow) * K + k0 + aK4];
        As[aK4 + 0][aRow] = av.x;
        As[aK4 + 1][aRow] = av.y;
        As[aK4 + 2][aRow] = av.z;
        As[aK4 + 3][aRow] = av.w;
        float4 bv = *(const float4*)&Bm[(size_t)(k0 + bK) * N + colBase + bC4];
        *(float4*)&Bs[bK][bC4] = bv;
        __syncthreads();
#pragma unroll
        for (int k = 0; k < 16; ++k) {
            float4 a = *(const float4*)&As[k][ty * 4];
            float4 b = *(const float4*)&Bs[k][tx * 4];
            float ar[4] = {a.x, a.y, a.z, a.w};
            float br[4] = {b.x, b.y, b.z, b.w};
#pragma unroll
            for (int i = 0; i < 4; ++i)
#pragma unroll
                for (int j = 0; j < 4; ++j)
                    loc[i][j] = fmaf(ar[i], br[j], loc[i][j]);
        }
        __syncthreads();
        if ((++tile & 7) == 0) {
#pragma unroll
            for (int i = 0; i < 4; ++i)
#pragma unroll
                for (int j = 0; j < 4; ++j) {
                    acc[i][j] += loc[i][j];
                    loc[i][j] = 0.0f;
                }
        }
    }
#pragma unroll
    for (int i = 0; i < 4; ++i)
#pragma unroll
        for (int j = 0; j < 4; ++j)
            acc[i][j] += loc[i][j];

#pragma unroll
    for (int i = 0; i < 4; ++i) {
        int r = rowBase + ty * 4 + i;
        int c = colBase + tx * 4;
        float4 v = make_float4(acc[i][0], acc[i][1], acc[i][2], acc[i][3]);
        if (dst < 0) {
            *(float4*)&Cext[(size_t)r * N + c] = v;
        } else {
            int b = r / LL, l = r % LL;
            int h = c >> 6, dh = c & 63;
            size_t idx = (((size_t)(b * H + h)) * LL + l) * 64 + dh;
            float* dp = (dst == 0) ? g_q : (dst == 1 ? g_k : g_v);
            *(float4*)&dp[idx] = v;
        }
    }
}

// ---------------------------------------------------------------------------
// RoPE in place on g_q (which=0, H=NH) or g_k (which=1, H=KVH).
// Bit-replicates the CPU reference chain:
//   p    = fl32(10000^e)        (glibc powf is correctly rounded -> double pow,
//                                rounded once, reproduces it exactly)
//   invf = fl32(1.0f / p)       (exact fp32 divide, two-rounding chain kept)
//   f    = fl32(pos * invf)     (reference's fp32 angle incl. its rounding)
//   cos/sin on the fp32 angle computed in double, rounded once
//   rotation with explicit mul/add rounding (no FMA contraction)
// ---------------------------------------------------------------------------
__global__ void rope_kernel(int which, int H, const int* __restrict__ pos)
{
    int idx = blockIdx.x * blockDim.x + threadIdx.x;
    int total = BB * H * LL * 32;
    if (idx >= total) return;
    int i    = idx & 31;
    int rest = idx >> 5;
    int l    = rest % LL;
    int bh   = rest / LL;
    int b    = bh / H;

    float* x = (which == 0 ? g_q : g_k) + ((size_t)bh * LL + l) * 64;

    float e    = (float)(2 * i) / 64.0f;                 // exact
    float p    = (float)pow(10000.0, (double)e);         // correctly rounded fp32
    float invf = __fdiv_rn(1.0f, p);                     // fp32 divide, like ref
    float f    = __fmul_rn((float)pos[b * LL + l], invf);// fp32 angle, like ref

    double fd = (double)f;
    float c = (float)cos(fd);                            // correctly rounded
    float s = (float)sin(fd);

    float x0 = x[i], x1 = x[i + 32];
    x[i]      = __fsub_rn(__fmul_rn(x0, c), __fmul_rn(x1, s));
    x[i + 32] = __fadd_rn(__fmul_rn(x1, c), __fmul_rn(x0, s));
}

// ---------------------------------------------------------------------------
// Scores: per (b,h): S[q,k] = 0.125 * dot(Q[b,h,q,:], K[b,h/2,k,:])
// grid (32, 32, B*NH), 64x64 tiles, Kdim = 64. Exact fp32.
// ---------------------------------------------------------------------------
__global__ __launch_bounds__(256) void gemm_scores()
{
    __shared__ float As[16][64];
    __shared__ float Bs[16][64];

    int z = blockIdx.z;                // b*NH + h
    int b = z / NHH, h = z % NHH;
    const float* Aq = g_q + (size_t)z * LL * DHH;
    const float* Bk = g_k + (size_t)(b * KVHH + (h >> 1)) * LL * DHH;
    float* C = g_scores + (size_t)z * LL * LL;

    int t  = threadIdx.x;
    int tx = t & 15, ty = t >> 4;
    int rowBase = blockIdx.y * 64;
    int colBase = blockIdx.x * 64;
    int aRow = t >> 2;
    int aK4  = (t & 3) * 4;

    float acc[4][4] = {};

    for (int k0 = 0; k0 < 64; k0 += 16) {
        float4 av = *(const float4*)&Aq[(size_t)(rowBase + aRow) * 64 + k0 + aK4];
        As[aK4 + 0][aRow] = av.x;
        As[aK4 + 1][aRow] = av.y;
        As[aK4 + 2][aRow] = av.z;
        As[aK4 + 3][aRow] = av.w;
        // B^T load: key rows of K become columns of the score tile
        float4 bv = *(const float4*)&Bk[(size_t)(colBase + aRow) * 64 + k0 + aK4];
        Bs[aK4 + 0][aRow] = bv.x;
        Bs[aK4 + 1][aRow] = bv.y;
        Bs[aK4 + 2][aRow] = bv.z;
        Bs[aK4 + 3][aRow] = bv.w;
        __syncthreads();
#pragma unroll
        for (int k = 0; k < 16; ++k) {
            float4 a = *(const float4*)&As[k][ty * 4];
            float4 b4 = *(const float4*)&Bs[k][tx * 4];
            float ar[4] = {a.x, a.y, a.z, a.w};
            float br[4] = {b4.x, b4.y, b4.z, b4.w};
#pragma unroll
            for (int i = 0; i < 4; ++i)
#pragma unroll
                for (int j = 0; j < 4; ++j)
                    acc[i][j] = fmaf(ar[i], br[j], acc[i][j]);
        }
        __syncthreads();
    }

#pragma unroll
    for (int i = 0; i < 4; ++i) {
        int r = rowBase + ty * 4 + i;
        int c = colBase + tx * 4;
        float4 v = make_float4(acc[i][0] * 0.125f, acc[i][1] * 0.125f,
                               acc[i][2] * 0.125f, acc[i][3] * 0.125f);
        *(float4*)&C[(size_t)r * LL + c] = v;
    }
}

// ---------------------------------------------------------------------------
// Per score row: exact top-1024 threshold via 4-pass radix select on
// order-preserving uint encoding, then masked softmax in place.
// One block (256 threads) per row, grid = B*NH*L.
// ---------------------------------------------------------------------------
__global__ __launch_bounds__(256) void topk_softmax()
{
    __shared__ float    s[2048];
    __shared__ unsigned u[2048];
    __shared__ int      hist[256];
    __shared__ float    red[256];
    __shared__ int      sel_d, sel_w;

    float* row = g_scores + (size_t)blockIdx.x * LL;
    int t = threadIdx.x;

    for (int j = t; j < 2048; j += 256) {
        float v = row[j];
        s[j] = v;
        unsigned bits = __float_as_uint(v);
        u[j] = (bits & 0x80000000u) ? ~bits : (bits | 0x80000000u);
    }
    __syncthreads();

    unsigned prefix = 0, prefmask = 0;
    int want = 1024;
    for (int pass = 0; pass < 4; ++pass) {
        int shift = 24 - pass * 8;
        hist[t] = 0;
        __syncthreads();
        for (int j = t; j < 2048; j += 256) {
            if ((u[j] & prefmask) == prefix)
                atomicAdd(&hist[(u[j] >> shift) & 255], 1);
        }
        __syncthreads();
        if (t == 0) {
            int cum = 0, d;
            for (d = 255; d >= 0; --d) {
                if (cum + hist[d] >= want) break;
                cum += hist[d];
            }
            sel_d = d;
            sel_w = want - cum;
        }
        __syncthreads();
        prefix |= ((unsigned)sel_d) << shift;
        prefmask |= 0xFFu << shift;
        want = sel_w;
        __syncthreads();
    }
    unsigned uth = prefix;   // bit pattern of the 1024-th largest value

    // row max (top element is always kept, so max over all == max over kept)
    float m = -INFINITY;
    for (int j = t; j < 2048; j += 256) m = fmaxf(m, s[j]);
    red[t] = m;
    __syncthreads();
    for (int o = 128; o > 0; o >>= 1) {
        if (t < o) red[t] = fmaxf(red[t], red[t + o]);
        __syncthreads();
    }
    float mx = red[0];
    __syncthreads();

    float sum = 0.0f;
    for (int j = t; j < 2048; j += 256) {
        float e = (u[j] >= uth) ? expf(s[j] - mx) : 0.0f;
        s[j] = e;
        sum += e;
    }
    red[t] = sum;
    __syncthreads();
    for (int o = 128; o > 0; o >>= 1) {
        if (t < o) red[t] += red[t + o];
        __syncthreads();
    }
    float inv = 1.0f / red[0];
    __syncthreads();

    for (int j = t; j < 2048; j += 256) row[j] = s[j] * inv;
}

// ---------------------------------------------------------------------------
// P @ V per head: O[2048,64] = P[2048,2048] @ V[2048,64],
// written to g_attn[(b*L + l)*1024 + h*64 + dh]. grid (1, 32, B*NH).
// ---------------------------------------------------------------------------
__global__ __launch_bounds__(256) void gemm_pv()
{
    __shared__ float As[16][64];
    __shared__ float Bs[16][64];

    int z = blockIdx.z;
    int b = z / NHH, h = z % NHH;
    const float* P = g_scores + (size_t)z * LL * LL;
    const float* V = g_v + (size_t)(b * KVHH + (h >> 1)) * LL * DHH;

    int t  = threadIdx.x;
    int tx = t & 15, ty = t >> 4;
    int rowBase = blockIdx.y * 64;
    int aRow = t >> 2;
    int aK4  = (t & 3) * 4;
    int bK   = t >> 4;
    int bC4  = (t & 15) * 4;

    float acc[4][4] = {};

    for (int k0 = 0; k0 < LL; k0 += 16) {
        float4 av = *(const float4*)&P[(size_t)(rowBase + aRow) * LL + k0 + aK4];
        As[aK4 + 0][aRow] = av.x;
        As[aK4 + 1][aRow] = av.y;
        As[aK4 + 2][aRow] = av.z;
        As[aK4 + 3][aRow] = av.w;
        float4 bv = *(const float4*)&V[(size_t)(k0 + bK) * 64 + bC4];
        *(float4*)&Bs[bK][bC4] = bv;
        __syncthreads();
#pragma unroll
        for (int k = 0; k < 16; ++k) {
            float4 a = *(const float4*)&As[k][ty * 4];
            float4 b4 = *(const float4*)&Bs[k][tx * 4];
            float ar[4] = {a.x, a.y, a.z, a.w};
            float br[4] = {b4.x, b4.y, b4.z, b4.w};
#pragma unroll
            for (int i = 0; i < 4; ++i)
#pragma unroll
                for (int j = 0; j < 4; ++j)
                    acc[i][j] = fmaf(ar[i], br[j], acc[i][j]);
        }
        __syncthreads();
    }

#pragma unroll
    for (int i = 0; i < 4; ++i) {
        int l = rowBase + ty * 4 + i;
        size_t idx = ((size_t)(b * LL + l)) * (NHH * DHH) + h * 64 + tx * 4;
        float4 v = make_float4(acc[i][0], acc[i][1], acc[i][2], acc[i][3]);
        *(float4*)&g_attn[idx] = v;
    }
}

// ---------------------------------------------------------------------------
extern "C" void kernel_launch(void* const* d_in, const int* in_sizes, int n_in,
                              void* d_out, int out_size)
{
    const float* hs  = (const float*)d_in[0];  // [B,L,D]
    const float* wq  = (const float*)d_in[1];  // [D, NH*DH]
    const float* wk  = (const float*)d_in[2];  // [D, KVH*DH]
    const float* wv  = (const float*)d_in[3];  // [D, KVH*DH]
    const float* wo  = (const float*)d_in[4];  // [NH*DH, D]
    const int*   pos = (const int*)d_in[5];    // [B,L]
    float* out = (float*)d_out;                // [B,L,D]

    dim3 blk(256);

    // QKV projections (head-split epilogue)
    gemm_plain<<<dim3((NHH * DHH) / 64, (BB * LL) / 64), blk>>>(
        hs, wq, nullptr, BB * LL, NHH * DHH, DD, 0, 0, NHH);
    gemm_plain<<<dim3((KVHH * DHH) / 64, (BB * LL) / 64), blk>>>(
        hs, wk, nullptr, BB * LL, KVHH * DHH, DD, 0, 1, KVHH);
    gemm_plain<<<dim3((KVHH * DHH) / 64, (BB * LL) / 64), blk>>>(
        hs, wv, nullptr, BB * LL, KVHH * DHH, DD, 0, 2, KVHH);

    // RoPE
    rope_kernel<<<(BB * NHH * LL * 32 + 255) / 256, 256>>>(0, NHH, pos);
    rope_kernel<<<(BB * KVHH * LL * 32 + 255) / 256, 256>>>(1, KVHH, pos);

    // Scores
    gemm_scores<<<dim3(LL / 64, LL / 64, BB * NHH), blk>>>();

    // Top-k + softmax (in place over g_scores)
    topk_softmax<<<BB * NHH * LL, 256>>>();

    // P @ V
    gemm_pv<<<dim3(1, LL / 64, BB * NHH), blk>>>();

    // Output projection
    gemm_plain<<<dim3(DD / 64, (BB * LL) / 64), blk>>>(
        nullptr, wo, out, BB * LL, DD, NHH * DHH, 1, -1, 0);
}

// round 10
// speedup vs baseline: 1.1385x; 1.1385x over previous
#include <cuda_runtime.h>
#include <math.h>

#define BB   2
#define LL   2048
#define DD   1024
#define NHH  16
#define KVHH 8
#define DHH  64

// ---------------- scratch (device globals; no allocation allowed) ----------
__device__ float g_q[(size_t)BB * NHH * LL * DHH];      // 16 MB  [b][h][l][dh]
__device__ float g_k[(size_t)BB * KVHH * LL * DHH];     // 8 MB   [b][kh][l][dh]
__device__ float g_v[(size_t)BB * KVHH * LL * DHH];     // 8 MB   [b][kh][l][dh]
__device__ float g_attn[(size_t)BB * LL * NHH * DHH];   // 16 MB  [b][l][h*64+dh]
__device__ float g_scores[(size_t)BB * NHH * LL * LL];  // 536 MB [bh][q][k]

// ---------------------------------------------------------------------------
// Tiled fp32 GEMM, 128x128 tile, 8x8 microtile, k-chunk 8.
// Chunked accumulation flushes every 16 chunks (=128 k), matching the
// previous kernel's flush boundaries bitwise.
// dst < 0 : write Cext row-major.
// dst >= 0: head-split epilogue into g_q/g_k/g_v with H heads.
// a_sel=1 : A comes from g_attn instead of Aext.
// ---------------------------------------------------------------------------
__global__ __launch_bounds__(256) void gemm_plain(
    const float* __restrict__ Aext, const float* __restrict__ Bm,
    float* __restrict__ Cext, int M, int N, int K,
    int a_sel, int dst, int H)
{
    __shared__ float As[8][128];
    __shared__ float Bs[8][128];
    const float* A = a_sel ? g_attn : Aext;

    int t  = threadIdx.x;
    int tx = t & 15, ty = t >> 4;          // 16x16 thread grid, 8x8 micro
    int rowBase = blockIdx.y * 128;
    int colBase = blockIdx.x * 128;

    int aRow = t >> 1;                     // 0..127
    int aK   = (t & 1) * 4;                // 0 or 4
    int bK   = t >> 5;                     // 0..7
    int bC4  = (t & 31) * 4;               // 0..124

    float acc[8][8] = {};
    float loc[8][8] = {};
    int chunk = 0;

    for (int k0 = 0; k0 < K; k0 += 8) {
        float4 av = *(const float4*)&A[(size_t)(rowBase + aRow) * K + k0 + aK];
        As[aK + 0][aRow] = av.x;
        As[aK + 1][aRow] = av.y;
        As[aK + 2][aRow] = av.z;
        As[aK + 3][aRow] = av.w;
        float4 bv = *(const float4*)&Bm[(size_t)(k0 + bK) * N + colBase + bC4];
        *(float4*)&Bs[bK][bC4] = bv;
        __syncthreads();
#pragma unroll
        for (int k = 0; k < 8; ++k) {
            float4 a0 = *(const float4*)&As[k][ty * 8];
            float4 a1 = *(const float4*)&As[k][ty * 8 + 4];
            float4 b0 = *(const float4*)&Bs[k][tx * 8];
            float4 b1 = *(const float4*)&Bs[k][tx * 8 + 4];
            float ar[8] = {a0.x, a0.y, a0.z, a0.w, a1.x, a1.y, a1.z, a1.w};
            float br[8] = {b0.x, b0.y, b0.z, b0.w, b1.x, b1.y, b1.z, b1.w};
#pragma unroll
            for (int i = 0; i < 8; ++i)
#pragma unroll
                for (int j = 0; j < 8; ++j)
                    loc[i][j] = fmaf(ar[i], br[j], loc[i][j]);
        }
        __syncthreads();
        if ((++chunk & 15) == 0) {
#pragma unroll
            for (int i = 0; i < 8; ++i)
#pragma unroll
                for (int j = 0; j < 8; ++j) {
                    acc[i][j] += loc[i][j];
                    loc[i][j] = 0.0f;
                }
        }
    }
#pragma unroll
    for (int i = 0; i < 8; ++i)
#pragma unroll
        for (int j = 0; j < 8; ++j)
            acc[i][j] += loc[i][j];

#pragma unroll
    for (int i = 0; i < 8; ++i) {
        int r = rowBase + ty * 8 + i;
#pragma unroll
        for (int jj = 0; jj < 2; ++jj) {
            int c = colBase + tx * 8 + jj * 4;
            float4 v = make_float4(acc[i][jj * 4 + 0], acc[i][jj * 4 + 1],
                                   acc[i][jj * 4 + 2], acc[i][jj * 4 + 3]);
            if (dst < 0) {
                *(float4*)&Cext[(size_t)r * N + c] = v;
            } else {
                int b = r / LL, l = r % LL;
                int h = c >> 6, dh = c & 63;
                size_t idx = (((size_t)(b * H + h)) * LL + l) * 64 + dh;
                float* dp = (dst == 0) ? g_q : (dst == 1 ? g_k : g_v);
                *(float4*)&dp[idx] = v;
            }
        }
    }
}

// ---------------------------------------------------------------------------
// Fused RoPE: one block per (b,l). 32 threads compute the (correctly rounded,
// reference-bit-exact) cos/sin chain ONCE into smem; all 256 threads apply the
// rotation to the 16 q heads + 8 k heads. Same math as before, 24x less FP64.
// ---------------------------------------------------------------------------
__global__ __launch_bounds__(256) void rope_fused(const int* __restrict__ pos)
{
    __shared__ float cs[32], sn[32];
    int bl = blockIdx.x;               // 0..B*L-1
    int b = bl / LL, l = bl % LL;
    int t = threadIdx.x;

    if (t < 32) {
        float e    = (float)(2 * t) / 64.0f;                  // exact
        float p    = (float)pow(10000.0, (double)e);          // correctly rounded fp32
        float invf = __fdiv_rn(1.0f, p);                      // fp32 divide, like ref
        float f    = __fmul_rn((float)pos[bl], invf);         // fp32 angle, like ref
        double fd  = (double)f;
        cs[t] = (float)cos(fd);                               // correctly rounded
        sn[t] = (float)sin(fd);
    }
    __syncthreads();

    // units: q heads 0..NHH-1, then k heads
    for (int w = t; w < (NHH + KVHH) * 32; w += 256) {
        int i  = w & 31;
        int hh = w >> 5;
        float* x;
        if (hh < NHH)
            x = g_q + (((size_t)(b * NHH + hh)) * LL + l) * 64;
        else
            x = g_k + (((size_t)(b * KVHH + (hh - NHH))) * LL + l) * 64;
        float c = cs[i], s = sn[i];
        float x0 = x[i], x1 = x[i + 32];
        x[i]      = __fsub_rn(__fmul_rn(x0, c), __fmul_rn(x1, s));
        x[i + 32] = __fadd_rn(__fmul_rn(x1, c), __fmul_rn(x0, s));
    }
}

// ---------------------------------------------------------------------------
// Scores: per (b,h): S[q,k] = 0.125 * dot(Q[b,h,q,:], K[b,h/2,k,:])
// 128x128 tile, 8x8 micro, ascending k (bitwise same accumulation as before).
// grid (16, 16, B*NH).
// ---------------------------------------------------------------------------
__global__ __launch_bounds__(256) void gemm_scores()
{
    __shared__ float As[8][128];
    __shared__ float Bs[8][128];

    int z = blockIdx.z;                // b*NH + h
    int b = z / NHH, h = z % NHH;
    const float* Aq = g_q + (size_t)z * LL * DHH;
    const float* Bk = g_k + (size_t)(b * KVHH + (h >> 1)) * LL * DHH;
    float* C = g_scores + (size_t)z * LL * LL;

    int t  = threadIdx.x;
    int tx = t & 15, ty = t >> 4;
    int rowBase = blockIdx.y * 128;
    int colBase = blockIdx.x * 128;
    int aRow = t >> 1;
    int aK   = (t & 1) * 4;

    float acc[8][8] = {};

    for (int k0 = 0; k0 < 64; k0 += 8) {
        float4 av = *(const float4*)&Aq[(size_t)(rowBase + aRow) * 64 + k0 + aK];
        As[aK + 0][aRow] = av.x;
        As[aK + 1][aRow] = av.y;
        As[aK + 2][aRow] = av.z;
        As[aK + 3][aRow] = av.w;
        float4 bv = *(const float4*)&Bk[(size_t)(colBase + aRow) * 64 + k0 + aK];
        Bs[aK + 0][aRow] = bv.x;
        Bs[aK + 1][aRow] = bv.y;
        Bs[aK + 2][aRow] = bv.z;
        Bs[aK + 3][aRow] = bv.w;
        __syncthreads();
#pragma unroll
        for (int k = 0; k < 8; ++k) {
            float4 a0 = *(const float4*)&As[k][ty * 8];
            float4 a1 = *(const float4*)&As[k][ty * 8 + 4];
            float4 b0 = *(const float4*)&Bs[k][tx * 8];
            float4 b1 = *(const float4*)&Bs[k][tx * 8 + 4];
            float ar[8] = {a0.x, a0.y, a0.z, a0.w, a1.x, a1.y, a1.z, a1.w};
            float br[8] = {b0.x, b0.y, b0.z, b0.w, b1.x, b1.y, b1.z, b1.w};
#pragma unroll
            for (int i = 0; i < 8; ++i)
#pragma unroll
                for (int j = 0; j < 8; ++j)
                    acc[i][j] = fmaf(ar[i], br[j], acc[i][j]);
        }
        __syncthreads();
    }

#pragma unroll
    for (int i = 0; i < 8; ++i) {
        int r = rowBase + ty * 8 + i;
#pragma unroll
        for (int jj = 0; jj < 2; ++jj) {
            int c = colBase + tx * 8 + jj * 4;
            float4 v = make_float4(acc[i][jj * 4 + 0] * 0.125f,
                                   acc[i][jj * 4 + 1] * 0.125f,
                                   acc[i][jj * 4 + 2] * 0.125f,
                                   acc[i][jj * 4 + 3] * 0.125f);
            *(float4*)&C[(size_t)r * LL + c] = v;
        }
    }
}

// ---------------------------------------------------------------------------
// Per score row: exact top-1024 threshold via 4-pass radix select, then
// masked softmax in place. One block (256 threads) per row.
// ---------------------------------------------------------------------------
__global__ __launch_bounds__(256) void topk_softmax()
{
    __shared__ float    s[2048];
    __shared__ unsigned u[2048];
    __shared__ int      hist[256];
    __shared__ float    red[256];
    __shared__ int      sel_d, sel_w;

    float* row = g_scores + (size_t)blockIdx.x * LL;
    int t = threadIdx.x;

    for (int j = t; j < 2048; j += 256) {
        float v = row[j];
        s[j] = v;
        unsigned bits = __float_as_uint(v);
        u[j] = (bits & 0x80000000u) ? ~bits : (bits | 0x80000000u);
    }
    __syncthreads();

    unsigned prefix = 0, prefmask = 0;
    int want = 1024;
    for (int pass = 0; pass < 4; ++pass) {
        int shift = 24 - pass * 8;
        hist[t] = 0;
        __syncthreads();
        for (int j = t; j < 2048; j += 256) {
            if ((u[j] & prefmask) == prefix)
                atomicAdd(&hist[(u[j] >> shift) & 255], 1);
        }
        __syncthreads();
        if (t == 0) {
            int cum = 0, d;
            for (d = 255; d >= 0; --d) {
                if (cum + hist[d] >= want) break;
                cum += hist[d];
            }
            sel_d = d;
            sel_w = want - cum;
        }
        __syncthreads();
        prefix |= ((unsigned)sel_d) << shift;
        prefmask |= 0xFFu << shift;
        want = sel_w;
        __syncthreads();
    }
    unsigned uth = prefix;   // bit pattern of the 1024-th largest value

    float m = -INFINITY;
    for (int j = t; j < 2048; j += 256) m = fmaxf(m, s[j]);
    red[t] = m;
    __syncthreads();
    for (int o = 128; o > 0; o >>= 1) {
        if (t < o) red[t] = fmaxf(red[t], red[t + o]);
        __syncthreads();
    }
    float mx = red[0];
    __syncthreads();

    float sum = 0.0f;
    for (int j = t; j < 2048; j += 256) {
        float e = (u[j] >= uth) ? expf(s[j] - mx) : 0.0f;
        s[j] = e;
        sum += e;
    }
    red[t] = sum;
    __syncthreads();
    for (int o = 128; o > 0; o >>= 1) {
        if (t < o) red[t] += red[t + o];
        __syncthreads();
    }
    float inv = 1.0f / red[0];
    __syncthreads();

    for (int j = t; j < 2048; j += 256) row[j] = s[j] * inv;
}

// ---------------------------------------------------------------------------
// P @ V per head: O[2048,64] = P[2048,2048] @ V[2048,64].
// 128x64 tile, 8x4 micro, ascending k. grid (1, 16, B*NH).
// ---------------------------------------------------------------------------
__global__ __launch_bounds__(256) void gemm_pv()
{
    __shared__ float As[8][128];   // P transposed: As[k][q]
    __shared__ float Bs[8][64];    // V direct:     Bs[k][dh]

    int z = blockIdx.z;
    int b = z / NHH, h = z % NHH;
    const float* P = g_scores + (size_t)z * LL * LL;
    const float* V = g_v + (size_t)(b * KVHH + (h >> 1)) * LL * DHH;

    int t  = threadIdx.x;
    int tx = t & 15, ty = t >> 4;      // cols tx*4, rows ty*8
    int rowBase = blockIdx.y * 128;
    int aRow = t >> 1;                 // 0..127
    int aK   = (t & 1) * 4;

    float acc[8][4] = {};

    for (int k0 = 0; k0 < LL; k0 += 8) {
        float4 av = *(const float4*)&P[(size_t)(rowBase + aRow) * LL + k0 + aK];
        As[aK + 0][aRow] = av.x;
        As[aK + 1][aRow] = av.y;
        As[aK + 2][aRow] = av.z;
        As[aK + 3][aRow] = av.w;
        if (t < 128) {
            int bk = t >> 4, bc = (t & 15) * 4;
            *(float4*)&Bs[bk][bc] = *(const float4*)&V[(size_t)(k0 + bk) * 64 + bc];
        }
        __syncthreads();
#pragma unroll
        for (int k = 0; k < 8; ++k) {
            float4 a0 = *(const float4*)&As[k][ty * 8];
            float4 a1 = *(const float4*)&As[k][ty * 8 + 4];
            float4 bq = *(const float4*)&Bs[k][tx * 4];
            float ar[8] = {a0.x, a0.y, a0.z, a0.w, a1.x, a1.y, a1.z, a1.w};
            float br[4] = {bq.x, bq.y, bq.z, bq.w};
#pragma unroll
            for (int i = 0; i < 8; ++i)
#pragma unroll
                for (int j = 0; j < 4; ++j)
                    acc[i][j] = fmaf(ar[i], br[j], acc[i][j]);
        }
        __syncthreads();
    }

#pragma unroll
    for (int i = 0; i < 8; ++i) {
        int l = rowBase + ty * 8 + i;
        size_t idx = ((size_t)(b * LL + l)) * (NHH * DHH) + h * 64 + tx * 4;
        float4 v = make_float4(acc[i][0], acc[i][1], acc[i][2], acc[i][3]);
        *(float4*)&g_attn[idx] = v;
    }
}

// ---------------------------------------------------------------------------
extern "C" void kernel_launch(void* const* d_in, const int* in_sizes, int n_in,
                              void* d_out, int out_size)
{
    const float* hs  = (const float*)d_in[0];  // [B,L,D]
    const float* wq  = (const float*)d_in[1];  // [D, NH*DH]
    const float* wk  = (const float*)d_in[2];  // [D, KVH*DH]
    const float* wv  = (const float*)d_in[3];  // [D, KVH*DH]
    const float* wo  = (const float*)d_in[4];  // [NH*DH, D]
    const int*   pos = (const int*)d_in[5];    // [B,L]
    float* out = (float*)d_out;                // [B,L,D]

    dim3 blk(256);

    // QKV projections (head-split epilogue)
    gemm_plain<<<dim3((NHH * DHH) / 128, (BB * LL) / 128), blk>>>(
        hs, wq, nullptr, BB * LL, NHH * DHH, DD, 0, 0, NHH);
    gemm_plain<<<dim3((KVHH * DHH) / 128, (BB * LL) / 128), blk>>>(
        hs, wk, nullptr, BB * LL, KVHH * DHH, DD, 0, 1, KVHH);
    gemm_plain<<<dim3((KVHH * DHH) / 128, (BB * LL) / 128), blk>>>(
        hs, wv, nullptr, BB * LL, KVHH * DHH, DD, 0, 2, KVHH);

    // RoPE (q + k in one fused launch)
    rope_fused<<<BB * LL, 256>>>(pos);

    // Scores
    gemm_scores<<<dim3(LL / 128, LL / 128, BB * NHH), blk>>>();

    // Top-k + softmax (in place over g_scores)
    topk_softmax<<<BB * NHH * LL, 256>>>();

    // P @ V
    gemm_pv<<<dim3(1, LL / 128, BB * NHH), blk>>>();

    // Output projection
    gemm_plain<<<dim3(DD / 128, (BB * LL) / 128), blk>>>(
        nullptr, wo, out, BB * LL, DD, NHH * DHH, 1, -1, 0);
}

// round 11
// speedup vs baseline: 1.5258x; 1.3402x over previous
#include <cuda_runtime.h>
#include <math.h>

#define BB   2
#define LL   2048
#define DD   1024
#define NHH  16
#define KVHH 8
#define DHH  64

// ---------------- scratch (device globals; no allocation allowed) ----------
__device__ float g_q[(size_t)BB * NHH * LL * DHH];      // 16 MB  [b][h][l][dh]
__device__ float g_k[(size_t)BB * KVHH * LL * DHH];     // 8 MB   [b][kh][l][dh]
__device__ float g_v[(size_t)BB * KVHH * LL * DHH];     // 8 MB   [b][kh][l][dh]
__device__ float g_attn[(size_t)BB * LL * NHH * DHH];   // 16 MB  [b][l][h*64+dh]
__device__ float g_scores[(size_t)BB * NHH * LL * LL];  // 536 MB [bh][q][k]

// ---------------------------------------------------------------------------
// Tiled fp32 GEMM, 128x128 tile, 8x8 microtile, k-chunk 16.
// Ascending k, chunk flush every 8 chunks (=128 k): bitwise-identical
// accumulation to the previous (passing) kernel.
// ---------------------------------------------------------------------------
__global__ __launch_bounds__(256) void gemm_plain(
    const float* __restrict__ Aext, const float* __restrict__ Bm,
    float* __restrict__ Cext, int M, int N, int K,
    int a_sel, int dst, int H)
{
    __shared__ float As[16][128];
    __shared__ float Bs[16][128];
    const float* A = a_sel ? g_attn : Aext;

    int t  = threadIdx.x;
    int tx = t & 15, ty = t >> 4;          // 16x16 thread grid, 8x8 micro
    int rowBase = blockIdx.y * 128;
    int colBase = blockIdx.x * 128;

    int aRow = t >> 1;                     // 0..127
    int aK8  = (t & 1) * 8;                // 0 or 8
    int bK   = t >> 5;                     // 0..7 (also handles bK+8)
    int bC4  = (t & 31) * 4;               // 0..124

    float acc[8][8] = {};
    float loc[8][8] = {};
    int chunk = 0;

    for (int k0 = 0; k0 < K; k0 += 16) {
        const float* ap = &A[(size_t)(rowBase + aRow) * K + k0 + aK8];
        float4 av0 = *(const float4*)ap;
        float4 av1 = *(const float4*)(ap + 4);
        As[aK8 + 0][aRow] = av0.x;
        As[aK8 + 1][aRow] = av0.y;
        As[aK8 + 2][aRow] = av0.z;
        As[aK8 + 3][aRow] = av0.w;
        As[aK8 + 4][aRow] = av1.x;
        As[aK8 + 5][aRow] = av1.y;
        As[aK8 + 6][aRow] = av1.z;
        As[aK8 + 7][aRow] = av1.w;
        float4 bv0 = *(const float4*)&Bm[(size_t)(k0 + bK) * N + colBase + bC4];
        float4 bv1 = *(const float4*)&Bm[(size_t)(k0 + bK + 8) * N + colBase + bC4];
        *(float4*)&Bs[bK][bC4]     = bv0;
        *(float4*)&Bs[bK + 8][bC4] = bv1;
        __syncthreads();
#pragma unroll
        for (int k = 0; k < 16; ++k) {
            float4 a0 = *(const float4*)&As[k][ty * 8];
            float4 a1 = *(const float4*)&As[k][ty * 8 + 4];
            float4 b0 = *(const float4*)&Bs[k][tx * 8];
            float4 b1 = *(const float4*)&Bs[k][tx * 8 + 4];
            float ar[8] = {a0.x, a0.y, a0.z, a0.w, a1.x, a1.y, a1.z, a1.w};
            float br[8] = {b0.x, b0.y, b0.z, b0.w, b1.x, b1.y, b1.z, b1.w};
#pragma unroll
            for (int i = 0; i < 8; ++i)
#pragma unroll
                for (int j = 0; j < 8; ++j)
                    loc[i][j] = fmaf(ar[i], br[j], loc[i][j]);
        }
        __syncthreads();
        if ((++chunk & 7) == 0) {                 // every 128 k, as before
#pragma unroll
            for (int i = 0; i < 8; ++i)
#pragma unroll
                for (int j = 0; j < 8; ++j) {
                    acc[i][j] += loc[i][j];
                    loc[i][j] = 0.0f;
                }
        }
    }
#pragma unroll
    for (int i = 0; i < 8; ++i)
#pragma unroll
        for (int j = 0; j < 8; ++j)
            acc[i][j] += loc[i][j];

#pragma unroll
    for (int i = 0; i < 8; ++i) {
        int r = rowBase + ty * 8 + i;
#pragma unroll
        for (int jj = 0; jj < 2; ++jj) {
            int c = colBase + tx * 8 + jj * 4;
            float4 v = make_float4(acc[i][jj * 4 + 0], acc[i][jj * 4 + 1],
                                   acc[i][jj * 4 + 2], acc[i][jj * 4 + 3]);
            if (dst < 0) {
                *(float4*)&Cext[(size_t)r * N + c] = v;
            } else {
                int b = r / LL, l = r % LL;
                int h = c >> 6, dh = c & 63;
                size_t idx = (((size_t)(b * H + h)) * LL + l) * 64 + dh;
                float* dp = (dst == 0) ? g_q : (dst == 1 ? g_k : g_v);
                *(float4*)&dp[idx] = v;
            }
        }
    }
}

// ---------------------------------------------------------------------------
// Fused RoPE: one block per (b,l); 32 threads build cos/sin once, 256 apply.
// Reference-bit-exact rounding chain (unchanged from passing kernel).
// ---------------------------------------------------------------------------
__global__ __launch_bounds__(256) void rope_fused(const int* __restrict__ pos)
{
    __shared__ float cs[32], sn[32];
    int bl = blockIdx.x;               // 0..B*L-1
    int b = bl / LL, l = bl % LL;
    int t = threadIdx.x;

    if (t < 32) {
        float e    = (float)(2 * t) / 64.0f;
        float p    = (float)pow(10000.0, (double)e);
        float invf = __fdiv_rn(1.0f, p);
        float f    = __fmul_rn((float)pos[bl], invf);
        double fd  = (double)f;
        cs[t] = (float)cos(fd);
        sn[t] = (float)sin(fd);
    }
    __syncthreads();

    for (int w = t; w < (NHH + KVHH) * 32; w += 256) {
        int i  = w & 31;
        int hh = w >> 5;
        float* x;
        if (hh < NHH)
            x = g_q + (((size_t)(b * NHH + hh)) * LL + l) * 64;
        else
            x = g_k + (((size_t)(b * KVHH + (hh - NHH))) * LL + l) * 64;
        float c = cs[i], s = sn[i];
        float x0 = x[i], x1 = x[i + 32];
        x[i]      = __fsub_rn(__fmul_rn(x0, c), __fmul_rn(x1, s));
        x[i + 32] = __fadd_rn(__fmul_rn(x1, c), __fmul_rn(x0, s));
    }
}

// ---------------------------------------------------------------------------
// Scores: per (b,h): S[q,k] = 0.125 * dot(Q[b,h,q,:], K[b,h/2,k,:])
// 128x128 tile, 8x8 micro, k-chunk 16, ascending k (bitwise-identical).
// grid (16, 16, B*NH).
// ---------------------------------------------------------------------------
__global__ __launch_bounds__(256) void gemm_scores()
{
    __shared__ float As[16][128];
    __shared__ float Bs[16][128];

    int z = blockIdx.z;                // b*NH + h
    int b = z / NHH, h = z % NHH;
    const float* Aq = g_q + (size_t)z * LL * DHH;
    const float* Bk = g_k + (size_t)(b * KVHH + (h >> 1)) * LL * DHH;
    float* C = g_scores + (size_t)z * LL * LL;

    int t  = threadIdx.x;
    int tx = t & 15, ty = t >> 4;
    int rowBase = blockIdx.y * 128;
    int colBase = blockIdx.x * 128;
    int aRow = t >> 1;
    int aK8  = (t & 1) * 8;

    float acc[8][8] = {};

    for (int k0 = 0; k0 < 64; k0 += 16) {
        const float* ap = &Aq[(size_t)(rowBase + aRow) * 64 + k0 + aK8];
        float4 av0 = *(const float4*)ap;
        float4 av1 = *(const float4*)(ap + 4);
        As[aK8 + 0][aRow] = av0.x;
        As[aK8 + 1][aRow] = av0.y;
        As[aK8 + 2][aRow] = av0.z;
        As[aK8 + 3][aRow] = av0.w;
        As[aK8 + 4][aRow] = av1.x;
        As[aK8 + 5][aRow] = av1.y;
        As[aK8 + 6][aRow] = av1.z;
        As[aK8 + 7][aRow] = av1.w;
        const float* bp = &Bk[(size_t)(colBase + aRow) * 64 + k0 + aK8];
        float4 bv0 = *(const float4*)bp;
        float4 bv1 = *(const float4*)(bp + 4);
        Bs[aK8 + 0][aRow] = bv0.x;
        Bs[aK8 + 1][aRow] = bv0.y;
        Bs[aK8 + 2][aRow] = bv0.z;
        Bs[aK8 + 3][aRow] = bv0.w;
        Bs[aK8 + 4][aRow] = bv1.x;
        Bs[aK8 + 5][aRow] = bv1.y;
        Bs[aK8 + 6][aRow] = bv1.z;
        Bs[aK8 + 7][aRow] = bv1.w;
        __syncthreads();
#pragma unroll
        for (int k = 0; k < 16; ++k) {
            float4 a0 = *(const float4*)&As[k][ty * 8];
            float4 a1 = *(const float4*)&As[k][ty * 8 + 4];
            float4 b0 = *(const float4*)&Bs[k][tx * 8];
            float4 b1 = *(const float4*)&Bs[k][tx * 8 + 4];
            float ar[8] = {a0.x, a0.y, a0.z, a0.w, a1.x, a1.y, a1.z, a1.w};
            float br[8] = {b0.x, b0.y, b0.z, b0.w, b1.x, b1.y, b1.z, b1.w};
#pragma unroll
            for (int i = 0; i < 8; ++i)
#pragma unroll
                for (int j = 0; j < 8; ++j)
                    acc[i][j] = fmaf(ar[i], br[j], acc[i][j]);
        }
        __syncthreads();
    }

#pragma unroll
    for (int i = 0; i < 8; ++i) {
        int r = rowBase + ty * 8 + i;
#pragma unroll
        for (int jj = 0; jj < 2; ++jj) {
            int c = colBase + tx * 8 + jj * 4;
            float4 v = make_float4(acc[i][jj * 4 + 0] * 0.125f,
                                   acc[i][jj * 4 + 1] * 0.125f,
                                   acc[i][jj * 4 + 2] * 0.125f,
                                   acc[i][jj * 4 + 3] * 0.125f);
            *(float4*)&C[(size_t)r * LL + c] = v;
        }
    }
}

// ---------------------------------------------------------------------------
// Per score row: exact top-1024 threshold via 4-pass radix select with a
// PARALLEL suffix scan (replaces the 256-iteration serial bin walk), then
// masked softmax in place. One block (256 threads) per row.
// ---------------------------------------------------------------------------
__global__ __launch_bounds__(256) void topk_softmax()
{
    __shared__ float    s[2048];
    __shared__ unsigned u[2048];
    __shared__ int      hist[256];
    __shared__ int      scn[256];
    __shared__ float    redm[8];
    __shared__ float    reds[8];
    __shared__ int      sel_d, sel_w;

    float* row = g_scores + (size_t)blockIdx.x * LL;
    float4* row4 = (float4*)row;
    int t = threadIdx.x;
    int lane = t & 31, wrp = t >> 5;

    for (int j = t; j < 512; j += 256) {
        float4 v = row4[j];
        int j4 = j * 4;
        s[j4 + 0] = v.x; s[j4 + 1] = v.y; s[j4 + 2] = v.z; s[j4 + 3] = v.w;
        unsigned b;
        b = __float_as_uint(v.x); u[j4 + 0] = (b & 0x80000000u) ? ~b : (b | 0x80000000u);
        b = __float_as_uint(v.y); u[j4 + 1] = (b & 0x80000000u) ? ~b : (b | 0x80000000u);
        b = __float_as_uint(v.z); u[j4 + 2] = (b & 0x80000000u) ? ~b : (b | 0x80000000u);
        b = __float_as_uint(v.w); u[j4 + 3] = (b & 0x80000000u) ? ~b : (b | 0x80000000u);
    }
    __syncthreads();

    unsigned prefix = 0, prefmask = 0;
    int want = 1024;
    for (int pass = 0; pass < 4; ++pass) {
        int shift = 24 - pass * 8;
        hist[t] = 0;
        __syncthreads();
        for (int j = t; j < 2048; j += 256) {
            unsigned uv = u[j];
            if ((uv & prefmask) == prefix)
                atomicAdd(&hist[(uv >> shift) & 255], 1);
        }
        __syncthreads();
        // parallel suffix-inclusive scan: scn[t] = sum_{d>=t} hist[d]
        int v = hist[t];
        scn[t] = v;
        __syncthreads();
#pragma unroll
        for (int off = 1; off < 256; off <<= 1) {
            int add = (t + off < 256) ? scn[t + off] : 0;
            __syncthreads();
            v += add;
            scn[t] = v;
            __syncthreads();
        }
        int excl = (t < 255) ? scn[t + 1] : 0;
        if (excl < want && want <= scn[t]) { sel_d = t; sel_w = want - excl; }
        __syncthreads();
        prefix |= ((unsigned)sel_d) << shift;
        prefmask |= 0xFFu << shift;
        want = sel_w;
        __syncthreads();
    }
    unsigned uth = prefix;   // bit pattern of the 1024-th largest value

    // row max (warp shuffles + 8-way smem)
    float m = -INFINITY;
    for (int j = t; j < 2048; j += 256) m = fmaxf(m, s[j]);
#pragma unroll
    for (int o = 16; o > 0; o >>= 1) m = fmaxf(m, __shfl_xor_sync(0xFFFFFFFFu, m, o));
    if (lane == 0) redm[wrp] = m;
    __syncthreads();
    float mx = redm[0];
#pragma unroll
    for (int i = 1; i < 8; ++i) mx = fmaxf(mx, redm[i]);

    float sum = 0.0f;
    for (int j = t; j < 2048; j += 256) {
        float e = (u[j] >= uth) ? __expf(s[j] - mx) : 0.0f;
        s[j] = e;
        sum += e;
    }
#pragma unroll
    for (int o = 16; o > 0; o >>= 1) sum += __shfl_xor_sync(0xFFFFFFFFu, sum, o);
    if (lane == 0) reds[wrp] = sum;
    __syncthreads();
    float tot = reds[0];
#pragma unroll
    for (int i = 1; i < 8; ++i) tot += reds[i];
    float inv = 1.0f / tot;

    for (int j = t; j < 512; j += 256) {
        int j4 = j * 4;
        float4 v = make_float4(s[j4 + 0] * inv, s[j4 + 1] * inv,
                               s[j4 + 2] * inv, s[j4 + 3] * inv);
        row4[j] = v;
    }
}

// ---------------------------------------------------------------------------
// P @ V per head: O[2048,64] = P[2048,2048] @ V[2048,64].
// 128x64 tile, 8x4 micro, k-chunk 16, ascending k. grid (1, 16, B*NH).
// ---------------------------------------------------------------------------
__global__ __launch_bounds__(256) void gemm_pv()
{
    __shared__ float As[16][128];   // P transposed: As[k][q]
    __shared__ float Bs[16][64];    // V direct:     Bs[k][dh]

    int z = blockIdx.z;
    int b = z / NHH, h = z % NHH;
    const float* P = g_scores + (size_t)z * LL * LL;
    const float* V = g_v + (size_t)(b * KVHH + (h >> 1)) * LL * DHH;

    int t  = threadIdx.x;
    int tx = t & 15, ty = t >> 4;      // cols tx*4, rows ty*8
    int rowBase = blockIdx.y * 128;
    int aRow = t >> 1;                 // 0..127
    int aK8  = (t & 1) * 8;
    int bk   = t >> 4;                 // 0..15
    int bc   = (t & 15) * 4;

    float acc[8][4] = {};

    for (int k0 = 0; k0 < LL; k0 += 16) {
        const float* ap = &P[(size_t)(rowBase + aRow) * LL + k0 + aK8];
        float4 av0 = *(const float4*)ap;
        float4 av1 = *(const float4*)(ap + 4);
        As[aK8 + 0][aRow] = av0.x;
        As[aK8 + 1][aRow] = av0.y;
        As[aK8 + 2][aRow] = av0.z;
        As[aK8 + 3][aRow] = av0.w;
        As[aK8 + 4][aRow] = av1.x;
        As[aK8 + 5][aRow] = av1.y;
        As[aK8 + 6][aRow] = av1.z;
        As[aK8 + 7][aRow] = av1.w;
        *(float4*)&Bs[bk][bc] = *(const float4*)&V[(size_t)(k0 + bk) * 64 + bc];
        __syncthreads();
#pragma unroll
        for (int k = 0; k < 16; ++k) {
            float4 a0 = *(const float4*)&As[k][ty * 8];
            float4 a1 = *(const float4*)&As[k][ty * 8 + 4];
            float4 bq = *(const float4*)&Bs[k][tx * 4];
            float ar[8] = {a0.x, a0.y, a0.z, a0.w, a1.x, a1.y, a1.z, a1.w};
            float br[4] = {bq.x, bq.y, bq.z, bq.w};
#pragma unroll
            for (int i = 0; i < 8; ++i)
#pragma unroll
                for (int j = 0; j < 4; ++j)
                    acc[i][j] = fmaf(ar[i], br[j], acc[i][j]);
        }
        __syncthreads();
    }

#pragma unroll
    for (int i = 0; i < 8; ++i) {
        int l = rowBase + ty * 8 + i;
        size_t idx = ((size_t)(b * LL + l)) * (NHH * DHH) + h * 64 + tx * 4;
        float4 v = make_float4(acc[i][0], acc[i][1], acc[i][2], acc[i][3]);
        *(float4*)&g_attn[idx] = v;
    }
}

// ---------------------------------------------------------------------------
extern "C" void kernel_launch(void* const* d_in, const int* in_sizes, int n_in,
                              void* d_out, int out_size)
{
    const float* hs  = (const float*)d_in[0];  // [B,L,D]
    const float* wq  = (const float*)d_in[1];  // [D, NH*DH]
    const float* wk  = (const float*)d_in[2];  // [D, KVH*DH]
    const float* wv  = (const float*)d_in[3];  // [D, KVH*DH]
    const float* wo  = (const float*)d_in[4];  // [NH*DH, D]
    const int*   pos = (const int*)d_in[5];    // [B,L]
    float* out = (float*)d_out;                // [B,L,D]

    dim3 blk(256);

    // QKV projections (head-split epilogue)
    gemm_plain<<<dim3((NHH * DHH) / 128, (BB * LL) / 128), blk>>>(
        hs, wq, nullptr, BB * LL, NHH * DHH, DD, 0, 0, NHH);
    gemm_plain<<<dim3((KVHH * DHH) / 128, (BB * LL) / 128), blk>>>(
        hs, wk, nullptr, BB * LL, KVHH * DHH, DD, 0, 1, KVHH);
    gemm_plain<<<dim3((KVHH * DHH) / 128, (BB * LL) / 128), blk>>>(
        hs, wv, nullptr, BB * LL, KVHH * DHH, DD, 0, 2, KVHH);

    // RoPE (q + k in one fused launch)
    rope_fused<<<BB * LL, 256>>>(pos);

    // Scores
    gemm_scores<<<dim3(LL / 128, LL / 128, BB * NHH), blk>>>();

    // Top-k + softmax (in place over g_scores)
    topk_softmax<<<BB * NHH * LL, 256>>>();

    // P @ V
    gemm_pv<<<dim3(1, LL / 128, BB * NHH), blk>>>();

    // Output projection
    gemm_plain<<<dim3(DD / 128, (BB * LL) / 128), blk>>>(
        nullptr, wo, out, BB * LL, DD, NHH * DHH, 1, -1, 0);
}